// round 1
// baseline (speedup 1.0000x reference)
#include <cuda_runtime.h>
#include <cstdint>

// BaseObservationModel: noisy = data + 0.1*noise; mask top-512 of rand per row
// of 2048; masked = where(mask, 0, noisy); mask_inverse = (!mask) as float.
//
// One CTA (256 threads) per row. Histogram-based exact top-k selection with
// jax.lax.top_k tie semantics (lower index wins among equal values).

#define D_DIM      2048
#define K_SEL      512
#define NTHREADS   256
#define NBINS      256

__global__ __launch_bounds__(NTHREADS)
void obs_model_kernel(const float* __restrict__ data,
                      const float* __restrict__ noise,
                      const float* __restrict__ rnd,
                      float* __restrict__ out_masked,
                      float* __restrict__ out_maskinv)
{
    __shared__ float          s_rand[D_DIM];
    __shared__ int            s_hist[NBINS];
    __shared__ int            s_cnt[NBINS];
    __shared__ int            s_cand[D_DIM];     // candidate original indices
    __shared__ unsigned char  s_mask[D_DIM];
    __shared__ int            s_ncand;
    __shared__ int            s_bstar;
    __shared__ int            s_m;

    const int tid = threadIdx.x;
    const size_t row_off = (size_t)blockIdx.x * D_DIM;

    // ---- init ----
    s_hist[tid] = 0;
    if (tid == 0) s_ncand = 0;
    __syncthreads();

    // ---- load rand (float4) + histogram ----
    const float4* r4 = (const float4*)(rnd + row_off);
    #pragma unroll
    for (int q = 0; q < 2; q++) {
        int e = tid + q * NTHREADS;           // float4 slot
        float4 v = r4[e];
        ((float4*)s_rand)[e] = v;
        int b0 = min(NBINS - 1, (int)(v.x * (float)NBINS));
        int b1 = min(NBINS - 1, (int)(v.y * (float)NBINS));
        int b2 = min(NBINS - 1, (int)(v.z * (float)NBINS));
        int b3 = min(NBINS - 1, (int)(v.w * (float)NBINS));
        atomicAdd(&s_hist[b0], 1);
        atomicAdd(&s_hist[b1], 1);
        atomicAdd(&s_hist[b2], 1);
        atomicAdd(&s_hist[b3], 1);
    }
    __syncthreads();

    // ---- inclusive suffix scan over bins: s_cnt[t] = #elements in bins >= t ----
    s_cnt[tid] = s_hist[tid];
    __syncthreads();
    #pragma unroll
    for (int off = 1; off < NBINS; off <<= 1) {
        int add = (tid + off < NBINS) ? s_cnt[tid + off] : 0;
        __syncthreads();
        s_cnt[tid] += add;
        __syncthreads();
    }

    // ---- locate threshold bin b*: cnt_ge[b*] >= K, cnt_ge[b*+1] < K ----
    {
        int ge      = s_cnt[tid];
        int ge_next = (tid < NBINS - 1) ? s_cnt[tid + 1] : 0;
        if (ge >= K_SEL && ge_next < K_SEL) {
            s_bstar = tid;
            s_m     = K_SEL - ge_next;   // how many to take from bin b* (>=1)
        }
    }
    __syncthreads();

    const int bstar = s_bstar;

    // ---- build preliminary mask + gather bin-b* candidates ----
    #pragma unroll
    for (int q = 0; q < 2; q++) {
        int e = tid + q * NTHREADS;
        int base = e * 4;
        #pragma unroll
        for (int l = 0; l < 4; l++) {
            int i = base + l;
            float v = s_rand[i];
            int b = min(NBINS - 1, (int)(v * (float)NBINS));
            unsigned char mk = 0;
            if (b > bstar) {
                mk = 1;                              // strictly above threshold bin
            } else if (b == bstar) {
                int slot = atomicAdd(&s_ncand, 1);   // needs exact ranking
                s_cand[slot] = i;
            }
            s_mask[i] = mk;
        }
    }
    __syncthreads();

    // ---- exact rank within threshold bin (jax.lax.top_k tie-break: lower idx first) ----
    {
        const int c = s_ncand;
        const int m = s_m;
        for (int i = tid; i < c; i += NTHREADS) {
            int   idx = s_cand[i];
            float v   = s_rand[idx];
            int   r   = 0;
            for (int j = 0; j < c; j++) {
                int   jdx = s_cand[j];
                float vj  = s_rand[jdx];
                r += (vj > v) || (vj == v && jdx < idx);
            }
            if (r < m) s_mask[idx] = 1;
        }
    }
    __syncthreads();

    // ---- stream data/noise, emit outputs ----
    const float4* d4 = (const float4*)(data + row_off);
    const float4* n4 = (const float4*)(noise + row_off);
    float4* om = (float4*)(out_masked + row_off);
    float4* oi = (float4*)(out_maskinv + row_off);

    #pragma unroll
    for (int q = 0; q < 2; q++) {
        int e = tid + q * NTHREADS;
        float4 dv = d4[e];
        float4 nv = n4[e];
        int base = e * 4;
        float4 o, mi;
        {
            bool mk = s_mask[base + 0];
            o.x  = mk ? 0.0f : fmaf(0.1f, nv.x, dv.x);
            mi.x = mk ? 0.0f : 1.0f;
        }
        {
            bool mk = s_mask[base + 1];
            o.y  = mk ? 0.0f : fmaf(0.1f, nv.y, dv.y);
            mi.y = mk ? 0.0f : 1.0f;
        }
        {
            bool mk = s_mask[base + 2];
            o.z  = mk ? 0.0f : fmaf(0.1f, nv.z, dv.z);
            mi.z = mk ? 0.0f : 1.0f;
        }
        {
            bool mk = s_mask[base + 3];
            o.w  = mk ? 0.0f : fmaf(0.1f, nv.w, dv.w);
            mi.w = mk ? 0.0f : 1.0f;
        }
        om[e] = o;
        oi[e] = mi;
    }
}

extern "C" void kernel_launch(void* const* d_in, const int* in_sizes, int n_in,
                              void* d_out, int out_size)
{
    const float* data  = (const float*)d_in[0];
    const float* noise = (const float*)d_in[1];
    const float* rnd   = (const float*)d_in[2];

    const size_t total = (size_t)in_sizes[0];       // 32*1024*2048
    const int rows = (int)(total / D_DIM);          // 32768

    float* out_masked  = (float*)d_out;
    float* out_maskinv = (float*)d_out + total;     // second output concatenated

    obs_model_kernel<<<rows, NTHREADS>>>(data, noise, rnd,
                                         out_masked, out_maskinv);
}

// round 3
// speedup vs baseline: 1.0693x; 1.0693x over previous
#include <cuda_runtime.h>
#include <cstdint>

// BaseObservationModel: noisy = data + 0.1*noise; mask top-512 of rand per
// row of 2048; masked = where(mask, 0, noisy); mask_inverse = !mask as f32.
//
// One CTA (256 threads) per row; each thread owns 8 elements (2 float4s) in
// REGISTERS through all phases. Cross-thread state: 256-bin histogram +
// threshold-bin candidates packed as order-preserving u64 keys.
// All 6 global loads are issued up front so DRAM latency overlaps selection.

#define D_DIM      2048
#define K_SEL      512
#define NTHREADS   256
#define NBINS      256

__global__ __launch_bounds__(NTHREADS)
void obs_model_kernel(const float4* __restrict__ data,
                      const float4* __restrict__ noise,
                      const float4* __restrict__ rnd,
                      float4* __restrict__ out_masked,
                      float4* __restrict__ out_maskinv)
{
    __shared__ int                s_hist[NBINS];
    __shared__ unsigned long long s_cand[D_DIM];   // packed (val_bits<<32)|~idx
    __shared__ int                s_ncand;
    __shared__ int                s_bstar;
    __shared__ int                s_m;

    const int tid = threadIdx.x;
    const size_t row4 = (size_t)blockIdx.x * (D_DIM / 4);

    s_hist[tid] = 0;
    if (tid == 0) s_ncand = 0;

    // ---- front-batch ALL global loads (rand, data, noise) ----
    float4 ra  = __ldcs(&rnd[row4 + tid]);
    float4 rb  = __ldcs(&rnd[row4 + tid + NTHREADS]);
    float4 dv0 = __ldcs(&data[row4 + tid]);
    float4 dv1 = __ldcs(&data[row4 + tid + NTHREADS]);
    float4 nv0 = __ldcs(&noise[row4 + tid]);
    float4 nv1 = __ldcs(&noise[row4 + tid + NTHREADS]);

    __syncthreads();   // s_hist / s_ncand init visible

    float v[8];
    v[0] = ra.x; v[1] = ra.y; v[2] = ra.z; v[3] = ra.w;
    v[4] = rb.x; v[5] = rb.y; v[6] = rb.z; v[7] = rb.w;

    int bin[8];
    #pragma unroll
    for (int j = 0; j < 8; j++) {
        bin[j] = min(NBINS - 1, (int)(v[j] * (float)NBINS));
        atomicAdd(&s_hist[bin[j]], 1);
    }
    __syncthreads();

    // ---- single-warp suffix scan over 256 bins; find threshold bin ----
    if (tid < 32) {
        int suf[8];
        {
            int run = 0;
            #pragma unroll
            for (int j = 7; j >= 0; j--) {
                run += s_hist[tid * 8 + j];
                suf[j] = run;
            }
        }
        int total = suf[0];
        int s = total;
        #pragma unroll
        for (int off = 1; off < 32; off <<= 1) {
            int t = __shfl_down_sync(0xffffffffu, s, off);
            if (tid + off < 32) s += t;
        }
        int excl = s - total;   // elems in bins owned by higher lanes
        #pragma unroll
        for (int j = 0; j < 8; j++) {
            int ge      = excl + suf[j];                       // cnt >= bin
            int ge_next = (j < 7) ? (excl + suf[j + 1]) : excl;
            if (ge >= K_SEL && ge_next < K_SEL) {
                s_bstar = tid * 8 + j;
                s_m     = K_SEL - ge_next;
            }
        }
    }
    __syncthreads();

    const int bstar = s_bstar;

    // ---- preliminary mask in registers; collect threshold-bin candidates ----
    unsigned mk = 0;     // bit j set => element j of this thread is masked
    #pragma unroll
    for (int j = 0; j < 8; j++) {
        if (bin[j] > bstar) {
            mk |= (1u << j);
        } else if (bin[j] == bstar) {
            int idx = (j < 4) ? (tid * 4 + j)
                              : ((tid + NTHREADS) * 4 + (j - 4));
            unsigned long long key =
                ((unsigned long long)__float_as_uint(v[j]) << 32)
                | (unsigned long long)(0xFFFFFFFFu - (unsigned)idx);
            int slot = atomicAdd(&s_ncand, 1);
            s_cand[slot] = key;
        }
    }
    __syncthreads();

    // ---- exact rank within threshold bin (lower index wins ties) ----
    {
        const int c = s_ncand;
        const int m = s_m;
        #pragma unroll
        for (int j = 0; j < 8; j++) {
            if (bin[j] == bstar) {
                int idx = (j < 4) ? (tid * 4 + j)
                                  : ((tid + NTHREADS) * 4 + (j - 4));
                unsigned long long key =
                    ((unsigned long long)__float_as_uint(v[j]) << 32)
                    | (unsigned long long)(0xFFFFFFFFu - (unsigned)idx);
                int r = 0;
                for (int t = 0; t < c; t++) r += (s_cand[t] > key);
                if (r < m) mk |= (1u << j);
            }
        }
    }
    // no barrier: mk is thread-private from here on

    // ---- emit both outputs (data/noise already in registers) ----
    {
        bool m0 = (mk >> 0) & 1, m1 = (mk >> 1) & 1;
        bool m2 = (mk >> 2) & 1, m3 = (mk >> 3) & 1;
        float4 o, mi;
        o.x  = m0 ? 0.0f : fmaf(0.1f, nv0.x, dv0.x);  mi.x = m0 ? 0.0f : 1.0f;
        o.y  = m1 ? 0.0f : fmaf(0.1f, nv0.y, dv0.y);  mi.y = m1 ? 0.0f : 1.0f;
        o.z  = m2 ? 0.0f : fmaf(0.1f, nv0.z, dv0.z);  mi.z = m2 ? 0.0f : 1.0f;
        o.w  = m3 ? 0.0f : fmaf(0.1f, nv0.w, dv0.w);  mi.w = m3 ? 0.0f : 1.0f;
        __stcs(&out_masked[row4 + tid],  o);
        __stcs(&out_maskinv[row4 + tid], mi);
    }
    {
        bool m0 = (mk >> 4) & 1, m1 = (mk >> 5) & 1;
        bool m2 = (mk >> 6) & 1, m3 = (mk >> 7) & 1;
        float4 o, mi;
        o.x  = m0 ? 0.0f : fmaf(0.1f, nv1.x, dv1.x);  mi.x = m0 ? 0.0f : 1.0f;
        o.y  = m1 ? 0.0f : fmaf(0.1f, nv1.y, dv1.y);  mi.y = m1 ? 0.0f : 1.0f;
        o.z  = m2 ? 0.0f : fmaf(0.1f, nv1.z, dv1.z);  mi.z = m2 ? 0.0f : 1.0f;
        o.w  = m3 ? 0.0f : fmaf(0.1f, nv1.w, dv1.w);  mi.w = m3 ? 0.0f : 1.0f;
        __stcs(&out_masked[row4 + tid + NTHREADS],  o);
        __stcs(&out_maskinv[row4 + tid + NTHREADS], mi);
    }
}

extern "C" void kernel_launch(void* const* d_in, const int* in_sizes, int n_in,
                              void* d_out, int out_size)
{
    const float4* data  = (const float4*)d_in[0];
    const float4* noise = (const float4*)d_in[1];
    const float4* rnd   = (const float4*)d_in[2];

    const size_t total = (size_t)in_sizes[0];        // 32*1024*2048
    const int rows = (int)(total / D_DIM);           // 32768

    float4* out_masked  = (float4*)d_out;
    float4* out_maskinv = (float4*)((float*)d_out + total);

    obs_model_kernel<<<rows, NTHREADS>>>(data, noise, rnd,
                                         out_masked, out_maskinv);
}